// round 2
// baseline (speedup 1.0000x reference)
#include <cuda_runtime.h>
#include <math.h>

// Problem constants
#define BATCH 4
#define SEQ   512
#define DIM   512
#define NH    8
#define HD    64
#define NL    6
#define DFFN  2048
#define VOCAB 32000
#define ROWS  (BATCH*SEQ)   // 2048

// ---------------- scratch (device globals; no allocation allowed) ----------
__device__ float g_x  [BATCH*SEQ*DIM];        // decoder / current activations
__device__ float g_enc[BATCH*SEQ*DIM];        // encoder activations / output
__device__ float g_q  [BATCH*SEQ*DIM];
__device__ float g_k  [BATCH*SEQ*DIM];
__device__ float g_v  [BATCH*SEQ*DIM];
__device__ float g_att[BATCH*SEQ*DIM];
__device__ float g_t  [BATCH*SEQ*DIM];        // GEMM staging before LN
__device__ float g_ffn[BATCH*SEQ*DFFN];
__device__ float g_sc [BATCH*NH*SEQ*SEQ];     // attention scores/probs

// ---------------- embedding + positional encoding ---------------------------
// Faithful to reference: fp64 angle = s / 10000^(2 d / 512); row 0 and col 0 -> 0;
// even d -> sin, odd d -> cos.
__global__ void k_embed(const int* __restrict__ tok, const float* __restrict__ emb,
                        float* __restrict__ out) {
    int idx = blockIdx.x * blockDim.x + threadIdx.x;   // < BATCH*SEQ*DIM
    int d  = idx & (DIM - 1);
    int bs = idx >> 9;                 // b*SEQ + s
    int s  = bs & (SEQ - 1);
    float pe = 0.f;
    if (s > 0 && d > 0) {
        double ang = (double)s / pow(10000.0, 2.0 * (double)d / (double)DIM);
        pe = (float)((d & 1) ? cos(ang) : sin(ang));
    }
    int t = tok[bs];
    out[idx] = emb[(size_t)t * DIM + d] + pe;
}

// ---------------- generic SGEMM: C = act(A@B + bias) ------------------------
// A: MxK row-major, B: KxN row-major, C: MxN.  M%64==0, N%64==0, K%16==0.
// act: 0 = none, 1 = leaky_relu(0.01)
__global__ void k_sgemm(int M, int N, int K,
                        const float* __restrict__ A, const float* __restrict__ B,
                        float* __restrict__ C, const float* __restrict__ bias, int act) {
    __shared__ float As[16][65];
    __shared__ float Bs[16][64];
    int tid  = threadIdx.x;              // 256 threads
    int row0 = blockIdx.y * 64;
    int col0 = blockIdx.x * 64;
    int tr   = (tid >> 4) << 2;          // 0..60
    int tc   = (tid & 15) << 2;          // 0..60
    float acc[4][4] = {};

    for (int k0 = 0; k0 < K; k0 += 16) {
#pragma unroll
        for (int i = 0; i < 4; i++) {
            int idx = tid + i * 256;          // 0..1023
            int m = idx >> 4, kk = idx & 15;
            As[kk][m] = A[(size_t)(row0 + m) * K + k0 + kk];
        }
#pragma unroll
        for (int i = 0; i < 4; i++) {
            int idx = tid + i * 256;
            int kk = idx >> 6, n = idx & 63;
            Bs[kk][n] = B[(size_t)(k0 + kk) * N + col0 + n];
        }
        __syncthreads();
#pragma unroll
        for (int kk = 0; kk < 16; kk++) {
            float a[4], b[4];
#pragma unroll
            for (int i = 0; i < 4; i++) a[i] = As[kk][tr + i];
#pragma unroll
            for (int j = 0; j < 4; j++) b[j] = Bs[kk][tc + j];
#pragma unroll
            for (int i = 0; i < 4; i++)
#pragma unroll
                for (int j = 0; j < 4; j++)
                    acc[i][j] = fmaf(a[i], b[j], acc[i][j]);
        }
        __syncthreads();
    }
#pragma unroll
    for (int i = 0; i < 4; i++) {
        int m = row0 + tr + i;
#pragma unroll
        for (int j = 0; j < 4; j++) {
            int n = col0 + tc + j;
            float v = acc[i][j];
            if (bias) v += bias[n];
            if (act) v = v > 0.f ? v : 0.01f * v;
            C[(size_t)m * N + n] = v;
        }
    }
}

// ---------------- attention scores: SC[b,h,q,k] = mask ? 1e-9 : (q.k)/8 -----
// grid (SEQ/64, SEQ/64, BATCH*NH), block 256
__global__ void k_scores(const float* __restrict__ Q, const float* __restrict__ Km,
                         const int* __restrict__ tok, int causal,
                         float* __restrict__ SC) {
    __shared__ float Qs[64][65];
    __shared__ float Ks[64][65];
    int z = blockIdx.z;                 // b*NH + h
    int b = z >> 3, h = z & 7;
    int q0 = blockIdx.y * 64, k0 = blockIdx.x * 64;
    int tid = threadIdx.x;
#pragma unroll
    for (int i = 0; i < 16; i++) {
        int idx = tid + i * 256;        // 0..4095
        int r = idx >> 6, d = idx & 63;
        Qs[r][d] = Q[((size_t)(b * SEQ) + q0 + r) * DIM + h * HD + d];
        Ks[r][d] = Km[((size_t)(b * SEQ) + k0 + r) * DIM + h * HD + d];
    }
    __syncthreads();
    int tr = (tid >> 4) << 2, tc = (tid & 15) << 2;
    float acc[4][4] = {};
#pragma unroll
    for (int d = 0; d < 64; d++) {
        float a[4], bb[4];
#pragma unroll
        for (int i = 0; i < 4; i++) a[i] = Qs[tr + i][d];
#pragma unroll
        for (int j = 0; j < 4; j++) bb[j] = Ks[tc + j][d];
#pragma unroll
        for (int i = 0; i < 4; i++)
#pragma unroll
            for (int j = 0; j < 4; j++)
                acc[i][j] = fmaf(a[i], bb[j], acc[i][j]);
    }
    float* out = SC + (size_t)z * SEQ * SEQ;
#pragma unroll
    for (int j = 0; j < 4; j++) {
        int k = k0 + tc + j;
        bool kmask = (tok[b * SEQ + k] == 0);
#pragma unroll
        for (int i = 0; i < 4; i++) {
            int q = q0 + tr + i;
            bool msk = kmask || (causal && k > q);
            out[(size_t)q * SEQ + k] = msk ? 1e-9f : acc[i][j] * 0.125f;
        }
    }
}

// ---------------- softmax over last dim (rows of 512) -----------------------
__global__ void k_softmax(float* __restrict__ SC) {
    int row = blockIdx.x;
    float* p = SC + (size_t)row * SEQ;
    __shared__ float red[256];
    int tid = threadIdx.x;
    float v0 = p[tid], v1 = p[tid + 256];
    red[tid] = fmaxf(v0, v1);
    __syncthreads();
    for (int s = 128; s > 0; s >>= 1) {
        if (tid < s) red[tid] = fmaxf(red[tid], red[tid + s]);
        __syncthreads();
    }
    float m = red[0];
    __syncthreads();
    float e0 = expf(v0 - m), e1 = expf(v1 - m);
    red[tid] = e0 + e1;
    __syncthreads();
    for (int s = 128; s > 0; s >>= 1) {
        if (tid < s) red[tid] += red[tid + s];
        __syncthreads();
    }
    float inv = 1.f / red[0];
    p[tid] = e0 * inv;
    p[tid + 256] = e1 * inv;
}

// ---------------- AV: O[b,q,h*64+d] = sum_k P[b,h,q,k] * V[b,k,h*64+d] ------
// grid (1, SEQ/64, BATCH*NH), block 256
__global__ void k_av(const float* __restrict__ P, const float* __restrict__ V,
                     float* __restrict__ O) {
    __shared__ float As[16][65];
    __shared__ float Bs[16][64];
    int z = blockIdx.z;
    int b = z >> 3, h = z & 7;
    int q0 = blockIdx.y * 64;
    int tid = threadIdx.x;
    int tr = (tid >> 4) << 2, tc = (tid & 15) << 2;
    float acc[4][4] = {};
    const float* Pz = P + (size_t)z * SEQ * SEQ;
    for (int k0 = 0; k0 < SEQ; k0 += 16) {
#pragma unroll
        for (int i = 0; i < 4; i++) {
            int idx = tid + i * 256;
            int m = idx >> 4, kk = idx & 15;
            As[kk][m] = Pz[(size_t)(q0 + m) * SEQ + k0 + kk];
        }
#pragma unroll
        for (int i = 0; i < 4; i++) {
            int idx = tid + i * 256;
            int kk = idx >> 6, n = idx & 63;
            Bs[kk][n] = V[((size_t)(b * SEQ) + k0 + kk) * DIM + h * HD + n];
        }
        __syncthreads();
#pragma unroll
        for (int kk = 0; kk < 16; kk++) {
            float a[4], bb[4];
#pragma unroll
            for (int i = 0; i < 4; i++) a[i] = As[kk][tr + i];
#pragma unroll
            for (int j = 0; j < 4; j++) bb[j] = Bs[kk][tc + j];
#pragma unroll
            for (int i = 0; i < 4; i++)
#pragma unroll
                for (int j = 0; j < 4; j++)
                    acc[i][j] = fmaf(a[i], bb[j], acc[i][j]);
        }
        __syncthreads();
    }
#pragma unroll
    for (int i = 0; i < 4; i++)
#pragma unroll
        for (int j = 0; j < 4; j++)
            O[((size_t)(b * SEQ) + q0 + tr + i) * DIM + h * HD + tc + j] = acc[i][j];
}

// ---------------- residual + LayerNorm: out = LN(t + r) * g + b -------------
// one block (256 threads) per row of 512
__global__ void k_lnres(const float* __restrict__ t, const float* __restrict__ r,
                        const float* __restrict__ g, const float* __restrict__ be,
                        float* __restrict__ out) {
    int row = blockIdx.x, tid = threadIdx.x;
    __shared__ float red[256];
    const float* tp = t + (size_t)row * DIM;
    const float* rp = r + (size_t)row * DIM;
    float a = tp[tid] + rp[tid];
    float b2 = tp[tid + 256] + rp[tid + 256];
    red[tid] = a + b2;
    __syncthreads();
    for (int s = 128; s > 0; s >>= 1) {
        if (tid < s) red[tid] += red[tid + s];
        __syncthreads();
    }
    float mean = red[0] * (1.f / DIM);
    __syncthreads();
    float da = a - mean, db = b2 - mean;
    red[tid] = da * da + db * db;
    __syncthreads();
    for (int s = 128; s > 0; s >>= 1) {
        if (tid < s) red[tid] += red[tid + s];
        __syncthreads();
    }
    float inv = 1.f / sqrtf(red[0] * (1.f / DIM) + 1e-6f);
    out[(size_t)row * DIM + tid]       = da * inv * g[tid] + be[tid];
    out[(size_t)row * DIM + tid + 256] = db * inv * g[tid + 256] + be[tid + 256];
}

// ---------------- host orchestration ---------------------------------------
static void mhsa(const float* xq, const float* xkv, const int* tok, int causal,
                 const float* Wq, const float* Wk, const float* Wv, const float* Wo,
                 const float* g1, const float* b1,
                 float* q, float* k, float* v, float* sc, float* att, float* t,
                 float* xout) {
    dim3 gP(DIM / 64, ROWS / 64);  // (8, 32)
    k_sgemm<<<gP, 256>>>(ROWS, DIM, DIM, xq,  Wq, q, nullptr, 0);
    k_sgemm<<<gP, 256>>>(ROWS, DIM, DIM, xkv, Wk, k, nullptr, 0);
    k_sgemm<<<gP, 256>>>(ROWS, DIM, DIM, xkv, Wv, v, nullptr, 0);
    k_scores<<<dim3(SEQ / 64, SEQ / 64, BATCH * NH), 256>>>(q, k, tok, causal, sc);
    k_softmax<<<BATCH * NH * SEQ, 256>>>(sc);
    k_av<<<dim3(1, SEQ / 64, BATCH * NH), 256>>>(sc, v, att);
    k_sgemm<<<gP, 256>>>(ROWS, DIM, DIM, att, Wo, t, nullptr, 0);
    k_lnres<<<ROWS, 256>>>(t, xq, g1, b1, xout);
}

static void ffn(float* xio, const float* W1, const float* c1,
                const float* W2, const float* c2, const float* g2, const float* b2,
                float* hbuf, float* t) {
    k_sgemm<<<dim3(DFFN / 64, ROWS / 64), 256>>>(ROWS, DFFN, DIM, xio, W1, hbuf, c1, 1);
    k_sgemm<<<dim3(DIM / 64, ROWS / 64), 256>>>(ROWS, DIM, DFFN, hbuf, W2, t, c2, 0);
    k_lnres<<<ROWS, 256>>>(t, xio, g2, b2, xio);
}

extern "C" void kernel_launch(void* const* d_in, const int* in_sizes, int n_in,
                              void* d_out, int out_size) {
    const int*   enc_tok = (const int*)d_in[0];
    const int*   dec_tok = (const int*)d_in[1];
    const float* emb_enc = (const float*)d_in[2];
    const float* emb_dec = (const float*)d_in[3];
    const float* projW   = (const float*)d_in[4];
    const float* ep[12];
    const float* dp[12];
    for (int i = 0; i < 12; i++) { ep[i] = (const float*)d_in[5 + i]; dp[i] = (const float*)d_in[17 + i]; }

    float *x, *enc, *q, *k, *v, *att, *t, *hffn, *sc;
    cudaGetSymbolAddress((void**)&x,    g_x);
    cudaGetSymbolAddress((void**)&enc,  g_enc);
    cudaGetSymbolAddress((void**)&q,    g_q);
    cudaGetSymbolAddress((void**)&k,    g_k);
    cudaGetSymbolAddress((void**)&v,    g_v);
    cudaGetSymbolAddress((void**)&att,  g_att);
    cudaGetSymbolAddress((void**)&t,    g_t);
    cudaGetSymbolAddress((void**)&hffn, g_ffn);
    cudaGetSymbolAddress((void**)&sc,   g_sc);

    const size_t wQ = (size_t)DIM * DIM;      // per-layer stride for Wq/Wk/Wv/Wo
    const size_t w1 = (size_t)DIM * DFFN;     // W1 and W2 per-layer stride
    // param index: 0 Wq, 1 Wk, 2 Wv, 3 Wo, 4 g1, 5 b1, 6 W1, 7 c1, 8 W2, 9 c2, 10 g2, 11 b2

    // ---- encoder ----
    k_embed<<<(BATCH * SEQ * DIM) / 256, 256>>>(enc_tok, emb_enc, enc);
    for (int l = 0; l < NL; l++) {
        mhsa(enc, enc, enc_tok, 0,
             ep[0] + l * wQ, ep[1] + l * wQ, ep[2] + l * wQ, ep[3] + l * wQ,
             ep[4] + l * DIM, ep[5] + l * DIM,
             q, k, v, sc, att, t, enc);
        ffn(enc, ep[6] + l * w1, ep[7] + l * DFFN, ep[8] + l * w1,
            ep[9] + l * DIM, ep[10] + l * DIM, ep[11] + l * DIM, hffn, t);
    }

    // ---- decoder ----
    k_embed<<<(BATCH * SEQ * DIM) / 256, 256>>>(dec_tok, emb_dec, x);
    for (int l = 0; l < NL; l++) {
        // self-attention (causal + pad mask on decoder tokens)
        mhsa(x, x, dec_tok, 1,
             dp[0] + l * wQ, dp[1] + l * wQ, dp[2] + l * wQ, dp[3] + l * wQ,
             dp[4] + l * DIM, dp[5] + l * DIM,
             q, k, v, sc, att, t, x);
        // cross-attention (same weights, kv = encoder output, encoder pad mask)
        mhsa(x, enc, enc_tok, 0,
             dp[0] + l * wQ, dp[1] + l * wQ, dp[2] + l * wQ, dp[3] + l * wQ,
             dp[4] + l * DIM, dp[5] + l * DIM,
             q, k, v, sc, att, t, x);
        ffn(x, dp[6] + l * w1, dp[7] + l * DFFN, dp[8] + l * w1,
            dp[9] + l * DIM, dp[10] + l * DIM, dp[11] + l * DIM, hffn, t);
    }

    // ---- final vocab projection: [2048,512] @ [512,32000] ----
    k_sgemm<<<dim3(VOCAB / 64, ROWS / 64), 256>>>(ROWS, VOCAB, DIM, x, projW,
                                                  (float*)d_out, nullptr, 0);
}

// round 4
// speedup vs baseline: 1.5357x; 1.5357x over previous
#include <cuda_runtime.h>
#include <cuda_bf16.h>
#include <math.h>
#include <stdint.h>

typedef __nv_bfloat16 bf16;

#define BATCH 4
#define SEQ   512
#define DIM   512
#define NH    8
#define NL    6
#define DFFN  2048
#define VOCAB 32000
#define ROWS  2048
#define NZ    32          // BATCH*NH

// ---- split-weight stack: each weight stored [N][3K] bf16 = [Bh|Bl|Bh] ------
#define SZA ((size_t)NL*DIM*3*DIM)     // Wq/Wk/Wv/Wo block: 4,718,592
#define SZF ((size_t)NL*DFFN*3*DIM)    // W1 [2048][1536] and W2 [512][6144]: 18,874,368
#define OFF_WQ 0
#define OFF_WK (SZA)
#define OFF_WV (2*SZA)
#define OFF_WO (3*SZA)
#define OFF_W1 (4*SZA)
#define OFF_W2 (4*SZA+SZF)
#define STACK  (4*SZA+2*SZF)
#define OFF_PJ (2*STACK)
#define WTOT   (OFF_PJ + (size_t)VOCAB*3*DIM)

__device__ __align__(256) bf16  g_w  [WTOT];            // all split weights
__device__ __align__(256) float g_x  [ROWS*DIM];        // decoder residual fp32
__device__ __align__(256) float g_enc[ROWS*DIM];        // encoder residual fp32
__device__ __align__(256) bf16  g_xsp[ROWS*3*DIM];      // [Ah|Ah|Al]
__device__ __align__(256) bf16  g_esp[ROWS*3*DIM];
__device__ __align__(256) bf16  g_qsp[NZ*SEQ*192];      // per-head Q split
__device__ __align__(256) bf16  g_ksp[NZ*SEQ*192];      // per-head K split (B-style)
__device__ __align__(256) float g_v  [ROWS*DIM];
__device__ __align__(256) bf16  g_vt [BATCH*DIM*3*SEQ]; // V^T split (B-style over s)
__device__ __align__(256) float g_sc [NZ*SEQ*SEQ];
__device__ __align__(256) bf16  g_psp[NZ*SEQ*3*SEQ];    // probs split (A-style)
__device__ __align__(256) bf16  g_asp[ROWS*3*DIM];      // attn out split (A-style)
__device__ __align__(256) bf16  g_hsp[ROWS*3*DFFN];     // FFN hidden split (A-style)
__device__ __align__(256) float g_t  [ROWS*DIM];

// ---------------- PTX helpers ------------------------------------------------
__device__ __forceinline__ uint32_t smem_u32(const void* p) {
    uint32_t a;
    asm("{ .reg .u64 t; cvta.to.shared.u64 t, %1; cvt.u32.u64 %0, t; }" : "=r"(a) : "l"(p));
    return a;
}
__device__ __forceinline__ void cpa16(uint32_t dst, const void* src) {
    asm volatile("cp.async.cg.shared.global [%0], [%1], 16;" :: "r"(dst), "l"(src));
}
#define CP_COMMIT() asm volatile("cp.async.commit_group;" ::: "memory")
#define CP_WAIT0()  asm volatile("cp.async.wait_group 0;" ::: "memory")

__device__ __forceinline__ void ldsm4(uint32_t (&r)[4], uint32_t a) {
    asm volatile("ldmatrix.sync.aligned.m8n8.x4.shared.b16 {%0,%1,%2,%3}, [%4];"
        : "=r"(r[0]), "=r"(r[1]), "=r"(r[2]), "=r"(r[3]) : "r"(a));
}
__device__ __forceinline__ void mma16816(float (&d)[4], const uint32_t (&a)[4],
                                         const uint32_t b0, const uint32_t b1) {
    asm volatile("mma.sync.aligned.m16n8k16.row.col.f32.bf16.bf16.f32 "
        "{%0,%1,%2,%3}, {%4,%5,%6,%7}, {%8,%9}, {%0,%1,%2,%3};"
        : "+f"(d[0]), "+f"(d[1]), "+f"(d[2]), "+f"(d[3])
        : "r"(a[0]), "r"(a[1]), "r"(a[2]), "r"(a[3]), "r"(b0), "r"(b1));
}
__device__ __forceinline__ void split2(float v, bf16& h, bf16& l) {
    h = __float2bfloat16(v);
    l = __float2bfloat16(v - __bfloat162float(h));
}

// ---------------- weight transpose + split: src[L,K,N] -> dst[L,N,3K] --------
__global__ void k_wsplit(const float* __restrict__ s, bf16* __restrict__ d, int K, int N) {
    __shared__ float ts[32][33];
    int n0 = blockIdx.x*32, k0 = blockIdx.y*32;
    s += (size_t)blockIdx.z*K*N;
    d += (size_t)blockIdx.z*N*3*K;
    int tx = threadIdx.x, ty = threadIdx.y;
#pragma unroll
    for (int i=0;i<4;i++) ts[ty+8*i][tx] = s[(size_t)(k0+ty+8*i)*N + n0+tx];
    __syncthreads();
#pragma unroll
    for (int i=0;i<4;i++) {
        float v = ts[tx][ty+8*i];           // (k=k0+tx, n=n0+ty+8i)
        bf16 h,l; split2(v,h,l);
        bf16* dp = d + (size_t)(n0+ty+8*i)*3*K + k0 + tx;
        dp[0]=h; dp[K]=l; dp[2*K]=h;        // B-style [Bh|Bl|Bh]
    }
}

// ---------------- V transpose+split: V[2048][512] -> vt[b][c][3*512] ---------
__global__ void k_vt(const float* __restrict__ V, bf16* __restrict__ VT) {
    __shared__ float ts[32][33];
    int b = blockIdx.z;
    int s0 = blockIdx.x*32, c0 = blockIdx.y*32;
    int tx = threadIdx.x, ty = threadIdx.y;
#pragma unroll
    for (int i=0;i<4;i++) ts[ty+8*i][tx] = V[((size_t)b*SEQ + s0+ty+8*i)*DIM + c0+tx];
    __syncthreads();
#pragma unroll
    for (int i=0;i<4;i++) {
        float v = ts[tx][ty+8*i];           // (s=s0+tx, c=c0+ty+8i)
        bf16 h,l; split2(v,h,l);
        bf16* dp = VT + ((size_t)b*DIM + c0+ty+8*i)*(3*SEQ) + s0 + tx;
        dp[0]=h; dp[SEQ]=l; dp[2*SEQ]=h;    // B-style [Vh|Vl|Vh]
    }
}

// ---------------- unified bf16 mma GEMM --------------------------------------
// C[M,N] = A[M,KK] @ B[N,KK]^T   (KK already = 3K split-concat)
// MODE: 0 plain (bias/act, fp32 C and/or A-style split S)
//       1 QK head-split (S=qsp/ksp, offsets in sO*)
//       2 scores (mask+scale -> fp32 C per z)
//       3 AV (batched, B=vt special offset, out -> asp A-style)
enum { EPI_PLAIN=0, EPI_QK=1, EPI_SCORES=2, EPI_AV=3 };

template<int BN, int MODE>
__global__ void __launch_bounds__(256) k_gemm(
    int M, int N, int KK,
    const bf16* __restrict__ A, const bf16* __restrict__ B,
    size_t aZ, size_t bZ, size_t cZ,
    float* __restrict__ C, bf16* __restrict__ S,
    int sO0, int sO1, int sO2, int sRS,
    const float* __restrict__ bias, int act,
    const int* __restrict__ tok, int causal)
{
    constexpr int BM = 128, BK = 64;
    constexpr int WN = BN/4;          // 32 or 16
    constexpr int NT = WN/8;          // 4 or 2
    constexpr int ASZ = BM*BK*2;      // 16384 B
    constexpr int BSZ = BN*BK*2;
    extern __shared__ char sm[];
    uint32_t smBase = smem_u32(sm);

    int tid = threadIdx.x, lane = tid&31, wid = tid>>5;
    int wm = wid>>2, wn = wid&3;
    int m0 = blockIdx.y*BM, n0 = blockIdx.x*BN;
    int z = blockIdx.z;
    A += (size_t)z*aZ;
    if (MODE==EPI_AV) B += (((size_t)(z>>3)*DIM) + (size_t)(z&7)*64) * (3*SEQ);
    else              B += (size_t)z*bZ;

    float acc[4][NT][4] = {};

    auto loadStage = [&](int t, int s) {
        uint32_t st = smBase + s*(ASZ+BSZ);
        int k0 = t*BK;
#pragma unroll
        for (int i=0;i<4;i++) {                      // A: 1024 16B chunks
            int idx = tid + i*256;
            int r = idx>>3, c = idx&7;
            cpa16(st + r*128 + ((c^(r&7))<<4), A + (size_t)(m0+r)*KK + k0 + c*8);
        }
#pragma unroll
        for (int i=0;i<BN/32;i++) {                  // B
            int idx = tid + i*256;
            int r = idx>>3, c = idx&7;
            cpa16(st + ASZ + r*128 + ((c^(r&7))<<4), B + (size_t)(n0+r)*KK + k0 + c*8);
        }
    };

    loadStage(0,0); CP_COMMIT();
    int KT = KK/BK;
    for (int t=0; t<KT; t++) {
        CP_WAIT0();
        __syncthreads();
        if (t+1 < KT) { loadStage(t+1, (t+1)&1); CP_COMMIT(); }
        uint32_t aB = smBase + (t&1)*(ASZ+BSZ);
        uint32_t bB = aB + ASZ;
#pragma unroll
        for (int ks=0; ks<4; ks++) {
            uint32_t af[4][4];
#pragma unroll
            for (int i=0;i<4;i++) {
                int r = wm*64 + i*16 + (lane&15);
                int c = ks*2 + (lane>>4);
                ldsm4(af[i], aB + r*128 + ((c^(r&7))<<4));
            }
            uint32_t bfr[NT][2];
#pragma unroll
            for (int j=0;j<NT;j+=2) {
                uint32_t q[4];
                int r = wn*WN + j*8 + (lane&7) + ((lane>>4)<<3);
                int c = ks*2 + ((lane>>3)&1);
                ldsm4(q, bB + r*128 + ((c^(r&7))<<4));
                bfr[j][0]=q[0]; bfr[j][1]=q[1]; bfr[j+1][0]=q[2]; bfr[j+1][1]=q[3];
            }
#pragma unroll
            for (int i=0;i<4;i++)
#pragma unroll
                for (int j=0;j<NT;j++)
                    mma16816(acc[i][j], af[i], bfr[j][0], bfr[j][1]);
        }
        __syncthreads();
    }

    // ---- epilogue ----
#pragma unroll
    for (int i=0;i<4;i++) {
#pragma unroll
        for (int j=0;j<NT;j++) {
#pragma unroll
            for (int r=0;r<4;r++) {
                int row = m0 + wm*64 + i*16 + (lane>>2) + ((r>>1)<<3);
                int col = n0 + wn*WN + j*8 + ((lane&3)<<1) + (r&1);
                float v = acc[i][j][r];
                if (MODE==EPI_PLAIN) {
                    if (bias) v += __ldg(&bias[col]);
                    if (act)  v = v>0.f ? v : 0.01f*v;
                    if (C) C[(size_t)z*cZ + (size_t)row*N + col] = v;
                    if (S) {
                        bf16 h,l; split2(v,h,l);
                        bf16* sp = S + (size_t)row*sRS;
                        sp[col+sO0]=h; sp[col+sO1]=h; sp[col+sO2]=l;
                    }
                } else if (MODE==EPI_QK) {
                    int b = row>>9, s = row&511, h = col>>6, d = col&63;
                    bf16* sp = S + ((size_t)((b<<3)+h)*SEQ + s)*192 + d;
                    bf16 hh,ll; split2(v,hh,ll);
                    sp[sO0]=hh; sp[sO1]=hh; sp[sO2]=ll;
                } else if (MODE==EPI_SCORES) {
                    bool mk = (tok[(z>>3)*SEQ + col]==0) || (causal && col>row);
                    C[(size_t)z*cZ + (size_t)row*SEQ + col] = mk ? 1e-9f : v*0.125f;
                } else { // EPI_AV
                    int grow = ((z>>3)<<9) + row;
                    int gcol = ((z&7)<<6) + col;
                    bf16 hh,ll; split2(v,hh,ll);
                    bf16* sp = S + (size_t)grow*(3*DIM);
                    sp[gcol]=hh; sp[gcol+DIM]=hh; sp[gcol+2*DIM]=ll;
                }
            }
        }
    }
}

// NOTE on EPI_QK offsets: Q (A-style) hi{0,64} lo{128}; K (B-style) hi{0,128} lo{64}.

// ---------------- embedding + PE (fp32 + A-style split) ----------------------
__global__ void k_embed(const int* __restrict__ tok, const float* __restrict__ emb,
                        float* __restrict__ o, bf16* __restrict__ os) {
    int idx = blockIdx.x*blockDim.x + threadIdx.x;
    int d = idx&(DIM-1), bs = idx>>9, s = bs&(SEQ-1);
    float pe = 0.f;
    if (s>0 && d>0) {
        double ang = (double)s / pow(10000.0, 2.0*(double)d/(double)DIM);
        pe = (float)((d&1) ? cos(ang) : sin(ang));
    }
    float v = emb[(size_t)tok[bs]*DIM + d] + pe;
    o[idx] = v;
    bf16 h,l; split2(v,h,l);
    bf16* sp = os + (size_t)bs*(3*DIM) + d;
    sp[0]=h; sp[DIM]=h; sp[2*DIM]=l;
}

// ---------------- softmax -> split probs (A-style) ---------------------------
__global__ void k_softmax(const float* __restrict__ SC, bf16* __restrict__ P) {
    int row = blockIdx.x, tid = threadIdx.x;
    const float* p = SC + (size_t)row*SEQ;
    __shared__ float red[256];
    float v0 = p[tid], v1 = p[tid+256];
    red[tid] = fmaxf(v0,v1);
    __syncthreads();
    for (int s=128;s>0;s>>=1) { if (tid<s) red[tid]=fmaxf(red[tid],red[tid+s]); __syncthreads(); }
    float m = red[0];
    __syncthreads();
    float e0 = expf(v0-m), e1 = expf(v1-m);
    red[tid] = e0+e1;
    __syncthreads();
    for (int s=128;s>0;s>>=1) { if (tid<s) red[tid]+=red[tid+s]; __syncthreads(); }
    float inv = 1.f/red[0];
    e0 *= inv; e1 *= inv;
    bf16* sp = P + (size_t)row*(3*SEQ);
    bf16 h,l;
    split2(e0,h,l); sp[tid]=h;     sp[SEQ+tid]=h;     sp[2*SEQ+tid]=l;
    split2(e1,h,l); sp[tid+256]=h; sp[SEQ+tid+256]=h; sp[2*SEQ+tid+256]=l;
}

// ---------------- residual + LN -> fp32 + A-style split ----------------------
__global__ void k_lnres(const float* __restrict__ t, const float* __restrict__ r,
                        const float* __restrict__ g, const float* __restrict__ be,
                        float* __restrict__ o, bf16* __restrict__ os) {
    int row = blockIdx.x, tid = threadIdx.x;
    __shared__ float red[256];
    size_t o0 = (size_t)row*DIM;
    float a  = t[o0+tid]     + r[o0+tid];
    float b2 = t[o0+tid+256] + r[o0+tid+256];
    red[tid] = a+b2;
    __syncthreads();
    for (int s=128;s>0;s>>=1) { if (tid<s) red[tid]+=red[tid+s]; __syncthreads(); }
    float mean = red[0]*(1.f/DIM);
    __syncthreads();
    float da = a-mean, db = b2-mean;
    red[tid] = da*da + db*db;
    __syncthreads();
    for (int s=128;s>0;s>>=1) { if (tid<s) red[tid]+=red[tid+s]; __syncthreads(); }
    float inv = 1.f/sqrtf(red[0]*(1.f/DIM) + 1e-6f);
    float va = da*inv*g[tid] + be[tid];
    float vb = db*inv*g[tid+256] + be[tid+256];
    o[o0+tid] = va; o[o0+tid+256] = vb;
    bf16* sp = os + (size_t)row*(3*DIM);
    bf16 h,l;
    split2(va,h,l); sp[tid]=h;     sp[DIM+tid]=h;     sp[2*DIM+tid]=l;
    split2(vb,h,l); sp[tid+256]=h; sp[DIM+tid+256]=h; sp[2*DIM+tid+256]=l;
}

// ---------------- host wrappers ----------------------------------------------
#define SM128 ((128*64 + 128*64)*2*2)   // 65536
#define SM64  ((128*64 + 64*64)*2*2)    // 49152

static void gemm_plain(int M, int N, int KK, const bf16* A, const bf16* B,
                       float* C, bf16* S, int sO0, int sO1, int sO2, int sRS,
                       const float* bias, int act) {
    k_gemm<128,EPI_PLAIN><<<dim3(N/128, M/128), 256, SM128>>>(
        M,N,KK, A,B, 0,0,0, C,S, sO0,sO1,sO2,sRS, bias,act, nullptr,0);
}
static void gemm_qk(const bf16* A, const bf16* W, bf16* S, int o0,int o1,int o2) {
    k_gemm<128,EPI_QK><<<dim3(4, 16), 256, SM128>>>(
        ROWS,DIM,3*DIM, A,W, 0,0,0, nullptr,S, o0,o1,o2,0, nullptr,0, nullptr,0);
}
static void gemm_scores(const bf16* Q, const bf16* K, float* SC, const int* tok, int causal) {
    k_gemm<128,EPI_SCORES><<<dim3(4, 4, NZ), 256, SM128>>>(
        SEQ,SEQ,192, Q,K, (size_t)SEQ*192,(size_t)SEQ*192,(size_t)SEQ*SEQ,
        SC,nullptr, 0,0,0,0, nullptr,0, tok,causal);
}
static void gemm_av(const bf16* P, const bf16* VT, bf16* S) {
    k_gemm<64,EPI_AV><<<dim3(1, 4, NZ), 256, SM64>>>(
        SEQ,64,3*SEQ, P,VT, (size_t)SEQ*3*SEQ,0,0,
        nullptr,S, 0,0,0,0, nullptr,0, nullptr,0);
}

extern "C" void kernel_launch(void* const* d_in, const int* in_sizes, int n_in,
                              void* d_out, int out_size) {
    const int*   etok = (const int*)d_in[0];
    const int*   dtok = (const int*)d_in[1];
    const float* eemb = (const float*)d_in[2];
    const float* demb = (const float*)d_in[3];
    const float* pw   = (const float*)d_in[4];
    const float* ep[12]; const float* dp[12];
    for (int i=0;i<12;i++) { ep[i]=(const float*)d_in[5+i]; dp[i]=(const float*)d_in[17+i]; }

    cudaFuncSetAttribute(k_gemm<128,EPI_PLAIN>,  cudaFuncAttributeMaxDynamicSharedMemorySize, SM128);
    cudaFuncSetAttribute(k_gemm<128,EPI_QK>,     cudaFuncAttributeMaxDynamicSharedMemorySize, SM128);
    cudaFuncSetAttribute(k_gemm<128,EPI_SCORES>, cudaFuncAttributeMaxDynamicSharedMemorySize, SM128);
    cudaFuncSetAttribute(k_gemm<64, EPI_AV>,     cudaFuncAttributeMaxDynamicSharedMemorySize, SM64);

    bf16 *w,*xsp,*esp,*qsp,*ksp,*vt,*psp,*asp,*hsp;
    float *x,*enc,*v,*sc,*t;
    cudaGetSymbolAddress((void**)&w,   g_w);
    cudaGetSymbolAddress((void**)&x,   g_x);   cudaGetSymbolAddress((void**)&enc, g_enc);
    cudaGetSymbolAddress((void**)&xsp, g_xsp); cudaGetSymbolAddress((void**)&esp, g_esp);
    cudaGetSymbolAddress((void**)&qsp, g_qsp); cudaGetSymbolAddress((void**)&ksp, g_ksp);
    cudaGetSymbolAddress((void**)&v,   g_v);   cudaGetSymbolAddress((void**)&vt,  g_vt);
    cudaGetSymbolAddress((void**)&sc,  g_sc);  cudaGetSymbolAddress((void**)&psp, g_psp);
    cudaGetSymbolAddress((void**)&asp, g_asp); cudaGetSymbolAddress((void**)&hsp, g_hsp);
    cudaGetSymbolAddress((void**)&t,   g_t);

    // ---- weight conversion: [K,N] fp32 -> [N,3K] bf16 ----
    dim3 wb(32,8);
    k_wsplit<<<dim3(DIM/32, DIM/32, NL),  wb>>>(ep[0], w+OFF_WQ, DIM, DIM);
    k_wsplit<<<dim3(DIM/32, DIM/32, NL),  wb>>>(ep[1], w+OFF_WK, DIM, DIM);
    k_wsplit<<<dim3(DIM/32, DIM/32, NL),  wb>>>(ep[2], w+OFF_WV, DIM, DIM);
    k_wsplit<<<dim3(DIM/32, DIM/32, NL),  wb>>>(ep[3], w+OFF_WO, DIM, DIM);
    k_wsplit<<<dim3(DFFN/32, DIM/32, NL), wb>>>(ep[6], w+OFF_W1, DIM, DFFN);
    k_wsplit<<<dim3(DIM/32, DFFN/32, NL), wb>>>(ep[8], w+OFF_W2, DFFN, DIM);
    k_wsplit<<<dim3(DIM/32, DIM/32, NL),  wb>>>(dp[0], w+STACK+OFF_WQ, DIM, DIM);
    k_wsplit<<<dim3(DIM/32, DIM/32, NL),  wb>>>(dp[1], w+STACK+OFF_WK, DIM, DIM);
    k_wsplit<<<dim3(DIM/32, DIM/32, NL),  wb>>>(dp[2], w+STACK+OFF_WV, DIM, DIM);
    k_wsplit<<<dim3(DIM/32, DIM/32, NL),  wb>>>(dp[3], w+STACK+OFF_WO, DIM, DIM);
    k_wsplit<<<dim3(DFFN/32, DIM/32, NL), wb>>>(dp[6], w+STACK+OFF_W1, DIM, DFFN);
    k_wsplit<<<dim3(DIM/32, DFFN/32, NL), wb>>>(dp[8], w+STACK+OFF_W2, DFFN, DIM);
    k_wsplit<<<dim3(VOCAB/32, DIM/32, 1), wb>>>(pw, w+OFF_PJ, DIM, VOCAB);

    const size_t wA = (size_t)DIM*3*DIM;        // per-layer att weight stride
    const size_t wF = (size_t)DFFN*3*DIM;       // per-layer FFN weight stride

    // ---- encoder ----
    k_embed<<<(ROWS*DIM)/256,256>>>(etok, eemb, enc, esp);
    for (int l=0;l<NL;l++) {
        const bf16 *Wq=w+OFF_WQ+l*wA, *Wk=w+OFF_WK+l*wA, *Wv=w+OFF_WV+l*wA, *Wo=w+OFF_WO+l*wA;
        gemm_qk(esp, Wq, qsp, 0,64,128);
        gemm_qk(esp, Wk, ksp, 0,128,64);
        gemm_plain(ROWS,DIM,3*DIM, esp, Wv, v, nullptr,0,0,0,0, nullptr,0);
        k_vt<<<dim3(16,16,BATCH), wb>>>(v, vt);
        gemm_scores(qsp, ksp, sc, etok, 0);
        k_softmax<<<NZ*SEQ,256>>>(sc, psp);
        gemm_av(psp, vt, asp);
        gemm_plain(ROWS,DIM,3*DIM, asp, Wo, t, nullptr,0,0,0,0, nullptr,0);
        k_lnres<<<ROWS,256>>>(t, enc, ep[4]+l*DIM, ep[5]+l*DIM, enc, esp);
        gemm_plain(ROWS,DFFN,3*DIM, esp, w+OFF_W1+l*wF, nullptr, hsp, 0,DFFN,2*DFFN,3*DFFN, ep[7]+l*DFFN, 1);
        gemm_plain(ROWS,DIM,3*DFFN, hsp, w+OFF_W2+l*wF, t, nullptr,0,0,0,0, ep[9]+l*DIM, 0);
        k_lnres<<<ROWS,256>>>(t, enc, ep[10]+l*DIM, ep[11]+l*DIM, enc, esp);
    }

    // ---- decoder ----
    k_embed<<<(ROWS*DIM)/256,256>>>(dtok, demb, x, xsp);
    for (int l=0;l<NL;l++) {
        const bf16 *Wq=w+STACK+OFF_WQ+l*wA, *Wk=w+STACK+OFF_WK+l*wA;
        const bf16 *Wv=w+STACK+OFF_WV+l*wA, *Wo=w+STACK+OFF_WO+l*wA;
        // self-attention (causal + dec pad mask)
        gemm_qk(xsp, Wq, qsp, 0,64,128);
        gemm_qk(xsp, Wk, ksp, 0,128,64);
        gemm_plain(ROWS,DIM,3*DIM, xsp, Wv, v, nullptr,0,0,0,0, nullptr,0);
        k_vt<<<dim3(16,16,BATCH), wb>>>(v, vt);
        gemm_scores(qsp, ksp, sc, dtok, 1);
        k_softmax<<<NZ*SEQ,256>>>(sc, psp);
        gemm_av(psp, vt, asp);
        gemm_plain(ROWS,DIM,3*DIM, asp, Wo, t, nullptr,0,0,0,0, nullptr,0);
        k_lnres<<<ROWS,256>>>(t, x, dp[4]+l*DIM, dp[5]+l*DIM, x, xsp);
        // cross-attention (same weights, kv = encoder out, enc pad mask)
        gemm_qk(xsp, Wq, qsp, 0,64,128);
        gemm_qk(esp, Wk, ksp, 0,128,64);
        gemm_plain(ROWS,DIM,3*DIM, esp, Wv, v, nullptr,0,0,0,0, nullptr,0);
        k_vt<<<dim3(16,16,BATCH), wb>>>(v, vt);
        gemm_scores(qsp, ksp, sc, etok, 0);
        k_softmax<<<NZ*SEQ,256>>>(sc, psp);
        gemm_av(psp, vt, asp);
        gemm_plain(ROWS,DIM,3*DIM, asp, Wo, t, nullptr,0,0,0,0, nullptr,0);
        k_lnres<<<ROWS,256>>>(t, x, dp[4]+l*DIM, dp[5]+l*DIM, x, xsp);
        // FFN
        gemm_plain(ROWS,DFFN,3*DIM, xsp, w+STACK+OFF_W1+l*wF, nullptr, hsp, 0,DFFN,2*DFFN,3*DFFN, dp[7]+l*DFFN, 1);
        gemm_plain(ROWS,DIM,3*DFFN, hsp, w+STACK+OFF_W2+l*wF, t, nullptr,0,0,0,0, dp[9]+l*DIM, 0);
        k_lnres<<<ROWS,256>>>(t, x, dp[10]+l*DIM, dp[11]+l*DIM, x, xsp);
    }

    // ---- final vocab projection ----
    gemm_plain(ROWS, VOCAB, 3*DIM, xsp, w+OFF_PJ, (float*)d_out, nullptr,0,0,0,0, nullptr,0);
}

// round 7
// speedup vs baseline: 1.9509x; 1.2703x over previous
#include <cuda_runtime.h>
#include <cuda_bf16.h>
#include <math.h>
#include <stdint.h>

typedef __nv_bfloat16 bf16;

#define BATCH 4
#define SEQ   512
#define DIM   512
#define NH    8
#define NL    6
#define DFFN  2048
#define VOCAB 32000
#define ROWS  2048
#define NZ    32

// ---- split-weight stack: every weight stored [N][3K] bf16 = [Bh|Bl|Bh] -----
#define QKVL   ((size_t)1536*1536)                 // fused QKV per-layer
#define OFF_QKV 0
#define OFF_WO (NL*QKVL)                           // [512][1536]
#define OFF_W1 (OFF_WO + (size_t)NL*512*1536)      // [2048][1536]
#define OFF_W2 (OFF_W1 + (size_t)NL*2048*1536)     // [512][6144]
#define STACK  (OFF_W2 + (size_t)NL*512*6144)
#define OFF_PJ (2*STACK)
#define WTOT   (OFF_PJ + (size_t)VOCAB*1536)

__device__ __align__(256) bf16  g_w  [WTOT];
__device__ __align__(256) float g_x  [ROWS*DIM];
__device__ __align__(256) float g_enc[ROWS*DIM];
__device__ __align__(256) bf16  g_xsp[ROWS*3*DIM];        // [Ah|Ah|Al]
__device__ __align__(256) bf16  g_esp[ROWS*3*DIM];
__device__ __align__(256) bf16  g_qsp[NZ*SEQ*192];        // per-head Q (A-style)
__device__ __align__(256) bf16  g_ksp[NZ*SEQ*192];        // per-head K (B-style)
__device__ __align__(256) float g_v  [ROWS*DIM];
__device__ __align__(256) bf16  g_vt [BATCH*DIM*3*SEQ];   // V^T split (B-style)
__device__ __align__(256) float g_sc [NZ*SEQ*SEQ];
__device__ __align__(256) bf16  g_psp[NZ*SEQ*3*SEQ];      // probs (A-style)
__device__ __align__(256) bf16  g_asp[ROWS*3*DIM];        // attn out (A-style)
__device__ __align__(256) bf16  g_hsp[ROWS*3*DFFN];       // FFN hidden (A-style)
__device__ __align__(256) float g_t  [2*ROWS*DIM];        // split-K partials

// ---------------- PTX helpers ------------------------------------------------
__device__ __forceinline__ uint32_t smem_u32(const void* p) {
    uint32_t a;
    asm("{ .reg .u64 t; cvta.to.shared.u64 t, %1; cvt.u32.u64 %0, t; }" : "=r"(a) : "l"(p));
    return a;
}
__device__ __forceinline__ void cpa16(uint32_t dst, const void* src) {
    asm volatile("cp.async.cg.shared.global [%0], [%1], 16;" :: "r"(dst), "l"(src));
}
#define CP_COMMIT() asm volatile("cp.async.commit_group;" ::: "memory")
#define CP_WAIT0()  asm volatile("cp.async.wait_group 0;" ::: "memory")
#define CP_WAIT1()  asm volatile("cp.async.wait_group 1;" ::: "memory")

__device__ __forceinline__ void ldsm4(uint32_t (&r)[4], uint32_t a) {
    asm volatile("ldmatrix.sync.aligned.m8n8.x4.shared.b16 {%0,%1,%2,%3}, [%4];"
        : "=r"(r[0]), "=r"(r[1]), "=r"(r[2]), "=r"(r[3]) : "r"(a));
}
__device__ __forceinline__ void mma16816(float (&d)[4], const uint32_t (&a)[4],
                                         const uint32_t b0, const uint32_t b1) {
    asm volatile("mma.sync.aligned.m16n8k16.row.col.f32.bf16.bf16.f32 "
        "{%0,%1,%2,%3}, {%4,%5,%6,%7}, {%8,%9}, {%0,%1,%2,%3};"
        : "+f"(d[0]), "+f"(d[1]), "+f"(d[2]), "+f"(d[3])
        : "r"(a[0]), "r"(a[1]), "r"(a[2]), "r"(a[3]), "r"(b0), "r"(b1));
}
__device__ __forceinline__ void split2(float v, bf16& h, bf16& l) {
    h = __float2bfloat16(v);
    l = __float2bfloat16(v - __bfloat162float(h));
}

// ---------------- weight transpose + split: src[z,K,N] -> dst[z(dZ),N,3K] ----
__global__ void k_wsplit(const float* __restrict__ s, bf16* __restrict__ d,
                         int K, int N, size_t dZ) {
    __shared__ float ts[32][33];
    int n0 = blockIdx.x*32, k0 = blockIdx.y*32;
    s += (size_t)blockIdx.z*K*N;
    d += (size_t)blockIdx.z*dZ;
    int tx = threadIdx.x, ty = threadIdx.y;
#pragma unroll
    for (int i=0;i<4;i++) ts[ty+8*i][tx] = s[(size_t)(k0+ty+8*i)*N + n0+tx];
    __syncthreads();
#pragma unroll
    for (int i=0;i<4;i++) {
        float v = ts[tx][ty+8*i];
        bf16 h,l; split2(v,h,l);
        bf16* dp = d + (size_t)(n0+ty+8*i)*3*K + k0 + tx;
        dp[0]=h; dp[K]=l; dp[2*K]=h;          // B-style [Bh|Bl|Bh]
    }
}

// ---------------- V transpose + split: V[2048][512] -> vt[b][c][3*512] -------
__global__ void k_vt(const float* __restrict__ V, bf16* __restrict__ VT) {
    __shared__ float ts[32][33];
    int b = blockIdx.z;
    int s0 = blockIdx.x*32, c0 = blockIdx.y*32;
    int tx = threadIdx.x, ty = threadIdx.y;
#pragma unroll
    for (int i=0;i<4;i++) ts[ty+8*i][tx] = V[((size_t)b*SEQ + s0+ty+8*i)*DIM + c0+tx];
    __syncthreads();
#pragma unroll
    for (int i=0;i<4;i++) {
        float v = ts[tx][ty+8*i];
        bf16 h,l; split2(v,h,l);
        bf16* dp = VT + ((size_t)b*DIM + c0+ty+8*i)*(3*SEQ) + s0 + tx;
        dp[0]=h; dp[SEQ]=l; dp[2*SEQ]=h;      // B-style
    }
}

// ---------------- unified bf16 mma GEMM --------------------------------------
enum { EPI_PLAIN=0, EPI_QKV=1, EPI_SCORES=2, EPI_AV=3 };

template<int BM, int BN, int MODE>
__global__ void __launch_bounds__(256) k_gemm(
    int M, int N, int KK,
    const bf16* __restrict__ A, const bf16* __restrict__ B,
    int aRS, int bRS, size_t aZ, size_t bZ, size_t cZ,
    float* __restrict__ C, bf16* __restrict__ S, bf16* __restrict__ S2,
    int secOff, int sO0, int sO1, int sO2, int sRS,
    const float* __restrict__ bias, int act,
    const int* __restrict__ tok, int causal)
{
    constexpr int ASZ = BM*128;         // bytes per stage (64 bf16 cols)
    constexpr int BSZ = BN*128;
    constexpr int STG = ASZ+BSZ;
    constexpr int AM  = BM/32;          // 16-row frags per warp
    constexpr int NT  = BN/32;          // 8-col frags per warp
    constexpr int WME = BM/2;           // warp M extent (2 warp-rows)
    constexpr int WNE = BN/4;           // warp N extent (4 warp-cols)
    extern __shared__ char sm[];
    uint32_t smBase = smem_u32(sm);

    int tid=threadIdx.x, lane=tid&31, wid=tid>>5;
    int wm=wid>>2, wn=wid&3;
    int m0=blockIdx.y*BM, n0=blockIdx.x*BN;
    int z=blockIdx.z;
    A += (size_t)z*aZ;
    if (MODE==EPI_AV) B += (((size_t)(z>>3)*DIM) + (size_t)(z&7)*64) * 1536;
    else              B += (size_t)z*bZ;

    float acc[AM][NT][4];
#pragma unroll
    for (int i=0;i<AM;i++)
#pragma unroll
        for (int j=0;j<NT;j++)
#pragma unroll
            for (int r=0;r<4;r++) acc[i][j][r]=0.f;

    auto loadStage = [&](int t, int s) {
        uint32_t st = smBase + s*STG;
        int k0 = t*64;
#pragma unroll
        for (int i=0;i<BM/32;i++) {
            int idx = tid + i*256;
            int r = idx>>3, c = idx&7;
            cpa16(st + r*128 + ((c^(r&7))<<4), A + (size_t)(m0+r)*aRS + k0 + c*8);
        }
#pragma unroll
        for (int i=0;i<BN/32;i++) {
            int idx = tid + i*256;
            int r = idx>>3, c = idx&7;
            cpa16(st + ASZ + r*128 + ((c^(r&7))<<4), B + (size_t)(n0+r)*bRS + k0 + c*8);
        }
    };

    int KT = KK/64;
    loadStage(0,0); CP_COMMIT();
    if (KT>1) { loadStage(1,1); CP_COMMIT(); }

    for (int t=0; t<KT; t++) {
        if (t+2<KT) CP_WAIT1(); else CP_WAIT0();
        __syncthreads();
        if (t+2<KT) { loadStage(t+2, (t+2)%3); CP_COMMIT(); }
        uint32_t aB = smBase + (t%3)*STG;
        uint32_t bB = aB + ASZ;
#pragma unroll
        for (int ks=0; ks<4; ks++) {
            uint32_t af[AM][4];
#pragma unroll
            for (int i=0;i<AM;i++) {
                int r = wm*WME + i*16 + (lane&15);
                int c = ks*2 + (lane>>4);
                ldsm4(af[i], aB + r*128 + ((c^(r&7))<<4));
            }
            uint32_t bfr[NT][2];
#pragma unroll
            for (int j=0;j<NT;j+=2) {
                uint32_t q[4];
                int r = wn*WNE + j*8 + (lane&7) + ((lane>>4)<<3);
                int c = ks*2 + ((lane>>3)&1);
                ldsm4(q, bB + r*128 + ((c^(r&7))<<4));
                bfr[j][0]=q[0]; bfr[j][1]=q[1]; bfr[j+1][0]=q[2]; bfr[j+1][1]=q[3];
            }
#pragma unroll
            for (int i=0;i<AM;i++)
#pragma unroll
                for (int j=0;j<NT;j++)
                    mma16816(acc[i][j], af[i], bfr[j][0], bfr[j][1]);
        }
    }

    // ---- epilogue ----
#pragma unroll
    for (int i=0;i<AM;i++) {
#pragma unroll
        for (int j=0;j<NT;j++) {
#pragma unroll
            for (int r=0;r<4;r++) {
                int row = m0 + wm*WME + i*16 + (lane>>2) + ((r>>1)<<3);
                int col = n0 + wn*WNE + j*8 + ((lane&3)<<1) + (r&1);
                float v = acc[i][j][r];
                if (MODE==EPI_PLAIN) {
                    if (bias && z==0) v += __ldg(&bias[col]);
                    if (act)  v = v>0.f ? v : 0.01f*v;
                    if (C) C[(size_t)z*cZ + (size_t)row*N + col] = v;
                    if (S) {
                        bf16 h,l; split2(v,h,l);
                        bf16* sp = S + (size_t)row*sRS;
                        sp[col+sO0]=h; sp[col+sO1]=h; sp[col+sO2]=l;
                    }
                } else if (MODE==EPI_QKV) {
                    int gc = col + secOff;
                    int b = row>>9, s = row&511;
                    if (gc < 512) {            // Q: A-style per head
                        int h = gc>>6, d = gc&63;
                        bf16* sp = S + ((size_t)((b<<3)+h)*512 + s)*192 + d;
                        bf16 hh,ll; split2(v,hh,ll);
                        sp[0]=hh; sp[64]=hh; sp[128]=ll;
                    } else if (gc < 1024) {    // K: B-style per head
                        int c = gc-512; int h = c>>6, d = c&63;
                        bf16* sp = S2 + ((size_t)((b<<3)+h)*512 + s)*192 + d;
                        bf16 hh,ll; split2(v,hh,ll);
                        sp[0]=hh; sp[64]=ll; sp[128]=hh;
                    } else {                   // V: fp32 staging
                        C[(size_t)row*512 + gc-1024] = v;
                    }
                } else if (MODE==EPI_SCORES) {
                    bool mk = (tok[(z>>3)*512 + col]==0) || (causal && col>row);
                    C[(size_t)z*cZ + (size_t)row*512 + col] = mk ? 1e-9f : v*0.125f;
                } else {                       // EPI_AV: A-style split attn out
                    int grow = ((z>>3)<<9) + row;
                    int gcol = ((z&7)<<6) + col;
                    bf16 hh,ll; split2(v,hh,ll);
                    bf16* sp = S + (size_t)grow*1536;
                    sp[gcol]=hh; sp[gcol+512]=hh; sp[gcol+1024]=ll;
                }
            }
        }
    }
}

// ---------------- embedding + PE ---------------------------------------------
__global__ void k_embed(const int* __restrict__ tok, const float* __restrict__ emb,
                        float* __restrict__ o, bf16* __restrict__ os) {
    int idx = blockIdx.x*blockDim.x + threadIdx.x;
    int d = idx&(DIM-1), bs = idx>>9, s = bs&(SEQ-1);
    float pe = 0.f;
    if (s>0 && d>0) {
        double ang = (double)s / pow(10000.0, 2.0*(double)d/(double)DIM);
        pe = (float)((d&1) ? cos(ang) : sin(ang));
    }
    float v = emb[(size_t)tok[bs]*DIM + d] + pe;
    o[idx] = v;
    bf16 h,l; split2(v,h,l);
    bf16* sp = os + (size_t)bs*(3*DIM) + d;
    sp[0]=h; sp[DIM]=h; sp[2*DIM]=l;
}

// ---------------- warp-per-row softmax -> split probs ------------------------
__global__ void k_softmax(const float* __restrict__ SC, bf16* __restrict__ P) {
    int row = blockIdx.x*8 + (threadIdx.x>>5);
    int lane = threadIdx.x&31;
    const float* p = SC + (size_t)row*SEQ;
    float v[16];
#pragma unroll
    for (int i=0;i<4;i++) {
        float4 f = *(const float4*)(p + i*128 + lane*4);
        v[4*i]=f.x; v[4*i+1]=f.y; v[4*i+2]=f.z; v[4*i+3]=f.w;
    }
    float m = v[0];
#pragma unroll
    for (int i=1;i<16;i++) m = fmaxf(m, v[i]);
#pragma unroll
    for (int o=16;o;o>>=1) m = fmaxf(m, __shfl_xor_sync(0xffffffffu, m, o));
    float s = 0.f;
#pragma unroll
    for (int i=0;i<16;i++) { v[i] = expf(v[i]-m); s += v[i]; }
#pragma unroll
    for (int o=16;o;o>>=1) s += __shfl_xor_sync(0xffffffffu, s, o);
    float inv = 1.f/s;
    bf16* sp = P + (size_t)row*1536;
#pragma unroll
    for (int i=0;i<4;i++) {
#pragma unroll
        for (int k=0;k<4;k++) {
            int idx = i*128 + lane*4 + k;
            bf16 h,l; split2(v[4*i+k]*inv, h, l);
            sp[idx]=h; sp[512+idx]=h; sp[1024+idx]=l;
        }
    }
}

// ---------------- residual + LN (sums split-K partials) ----------------------
__global__ void k_lnres(const float* __restrict__ t, const float* __restrict__ t2,
                        const float* __restrict__ r,
                        const float* __restrict__ g, const float* __restrict__ be,
                        float* __restrict__ o, bf16* __restrict__ os) {
    int row = blockIdx.x, tid = threadIdx.x;
    __shared__ float red[256];
    size_t o0 = (size_t)row*DIM;
    float a  = t[o0+tid]     + t2[o0+tid]     + r[o0+tid];
    float b2 = t[o0+tid+256] + t2[o0+tid+256] + r[o0+tid+256];
    red[tid] = a+b2;
    __syncthreads();
    for (int s=128;s>0;s>>=1) { if (tid<s) red[tid]+=red[tid+s]; __syncthreads(); }
    float mean = red[0]*(1.f/DIM);
    __syncthreads();
    float da = a-mean, db = b2-mean;
    red[tid] = da*da + db*db;
    __syncthreads();
    for (int s=128;s>0;s>>=1) { if (tid<s) red[tid]+=red[tid+s]; __syncthreads(); }
    float inv = 1.f/sqrtf(red[0]*(1.f/DIM) + 1e-6f);
    float va = da*inv*g[tid] + be[tid];
    float vb = db*inv*g[tid+256] + be[tid+256];
    o[o0+tid] = va; o[o0+tid+256] = vb;
    bf16 h,l;
    bf16* sp = os + (size_t)row*(3*DIM);
    split2(va,h,l); sp[tid]=h;     sp[DIM+tid]=h;     sp[2*DIM+tid]=l;
    split2(vb,h,l); sp[tid+256]=h; sp[DIM+tid+256]=h; sp[2*DIM+tid+256]=l;
}

// ---------------- host --------------------------------------------------------
#define SM_128_128 (3*(128+128)*128)   // 98304
#define SM_64_128  (3*(64+128)*128)    // 73728
#define SM_64_64   (3*(64+64)*128)     // 49152

extern "C" void kernel_launch(void* const* d_in, const int* in_sizes, int n_in,
                              void* d_out, int out_size) {
    const int*   etok = (const int*)d_in[0];
    const int*   dtok = (const int*)d_in[1];
    const float* eemb = (const float*)d_in[2];
    const float* demb = (const float*)d_in[3];
    const float* pw   = (const float*)d_in[4];
    const float* ep[12]; const float* dp[12];
    for (int i=0;i<12;i++) { ep[i]=(const float*)d_in[5+i]; dp[i]=(const float*)d_in[17+i]; }

    cudaFuncSetAttribute(k_gemm<128,128,EPI_PLAIN>,  cudaFuncAttributeMaxDynamicSharedMemorySize, SM_128_128);
    cudaFuncSetAttribute(k_gemm<128,128,EPI_QKV>,    cudaFuncAttributeMaxDynamicSharedMemorySize, SM_128_128);
    cudaFuncSetAttribute(k_gemm<128,128,EPI_SCORES>, cudaFuncAttributeMaxDynamicSharedMemorySize, SM_128_128);
    cudaFuncSetAttribute(k_gemm<64,128,EPI_PLAIN>,   cudaFuncAttributeMaxDynamicSharedMemorySize, SM_64_128);
    cudaFuncSetAttribute(k_gemm<64,128,EPI_QKV>,     cudaFuncAttributeMaxDynamicSharedMemorySize, SM_64_128);
    cudaFuncSetAttribute(k_gemm<64,64,EPI_AV>,       cudaFuncAttributeMaxDynamicSharedMemorySize, SM_64_64);

    bf16 *w,*xsp,*esp,*qsp,*ksp,*vt,*psp,*asp,*hsp;
    float *x,*enc,*v,*sc,*t;
    cudaGetSymbolAddress((void**)&w,   g_w);
    cudaGetSymbolAddress((void**)&x,   g_x);   cudaGetSymbolAddress((void**)&enc, g_enc);
    cudaGetSymbolAddress((void**)&xsp, g_xsp); cudaGetSymbolAddress((void**)&esp, g_esp);
    cudaGetSymbolAddress((void**)&qsp, g_qsp); cudaGetSymbolAddress((void**)&ksp, g_ksp);
    cudaGetSymbolAddress((void**)&v,   g_v);   cudaGetSymbolAddress((void**)&vt,  g_vt);
    cudaGetSymbolAddress((void**)&sc,  g_sc);  cudaGetSymbolAddress((void**)&psp, g_psp);
    cudaGetSymbolAddress((void**)&asp, g_asp); cudaGetSymbolAddress((void**)&hsp, g_hsp);
    cudaGetSymbolAddress((void**)&t,   g_t);
    float* t2 = t + (size_t)ROWS*DIM;

    // ---- weight conversion ----
    dim3 wb(32,8);
    for (int st=0; st<2; st++) {
        const float* const* P = st ? dp : ep;
        bf16* wq = w + st*STACK;
        k_wsplit<<<dim3(16,16,NL), wb>>>(P[0], wq+OFF_QKV,            512, 512, QKVL);
        k_wsplit<<<dim3(16,16,NL), wb>>>(P[1], wq+OFF_QKV+ 512*1536,  512, 512, QKVL);
        k_wsplit<<<dim3(16,16,NL), wb>>>(P[2], wq+OFF_QKV+1024*1536,  512, 512, QKVL);
        k_wsplit<<<dim3(16,16,NL), wb>>>(P[3], wq+OFF_WO,             512, 512, (size_t)512*1536);
        k_wsplit<<<dim3(64,16,NL), wb>>>(P[6], wq+OFF_W1,             512, 2048,(size_t)2048*1536);
        k_wsplit<<<dim3(16,64,NL), wb>>>(P[8], wq+OFF_W2,            2048, 512, (size_t)512*6144);
    }
    k_wsplit<<<dim3(1000,16,1), wb>>>(pw, w+OFF_PJ, 512, VOCAB, 0);

    const size_t MN = (size_t)ROWS*DIM;

    for (int st=0; st<2; st++) {
        const int*   tokA = st ? dtok : etok;
        const float* const* P = st ? dp : ep;
        bf16*  wq  = w + st*STACK;
        float* res = st ? x : enc;
        bf16*  rsp = st ? xsp : esp;

        k_embed<<<(ROWS*DIM)/256,256>>>(tokA, st?demb:eemb, res, rsp);

        for (int l=0; l<NL; l++) {
            const bf16* Wqkv = wq + OFF_QKV + l*QKVL;
            const bf16* Wo   = wq + OFF_WO + (size_t)l*512*1536;
            const bf16* W1   = wq + OFF_W1 + (size_t)l*2048*1536;
            const bf16* W2   = wq + OFF_W2 + (size_t)l*512*6144;
            int nAtt = st ? 2 : 1;
            for (int a=0; a<nAtt; a++) {
                const int* tokKV = (st && a==1) ? etok : tokA;
                int causal = (st && a==0) ? 1 : 0;
                if (!st || a==0) {
                    // fused QKV on current stream
                    k_gemm<128,128,EPI_QKV><<<dim3(12,16,1),256,SM_128_128>>>(
                        ROWS,1536,1536, rsp,Wqkv, 1536,1536, 0,0,0,
                        v, qsp,ksp, 0, 0,0,0,0, nullptr,0, nullptr,0);
                } else {
                    // cross: Q from x, K/V from encoder output
                    k_gemm<64,128,EPI_QKV><<<dim3(4,32,1),256,SM_64_128>>>(
                        ROWS,512,1536, rsp,Wqkv, 1536,1536, 0,0,0,
                        nullptr, qsp,nullptr, 0, 0,0,0,0, nullptr,0, nullptr,0);
                    k_gemm<128,128,EPI_QKV><<<dim3(8,16,1),256,SM_128_128>>>(
                        ROWS,1024,1536, esp,Wqkv+(size_t)512*1536, 1536,1536, 0,0,0,
                        v, nullptr,ksp, 512, 0,0,0,0, nullptr,0, nullptr,0);
                }
                k_vt<<<dim3(16,16,BATCH), wb>>>(v, vt);
                k_gemm<128,128,EPI_SCORES><<<dim3(4,4,NZ),256,SM_128_128>>>(
                    SEQ,SEQ,192, qsp,ksp, 192,192, (size_t)SEQ*192,(size_t)SEQ*192,(size_t)SEQ*SEQ,
                    sc, nullptr,nullptr, 0, 0,0,0,0, nullptr,0, tokKV,causal);
                k_softmax<<<NZ*SEQ/8,256>>>(sc, psp);
                k_gemm<64,64,EPI_AV><<<dim3(1,8,NZ),256,SM_64_64>>>(
                    SEQ,64,1536, psp,vt, 1536,1536, (size_t)SEQ*1536,0,0,
                    nullptr, asp,nullptr, 0, 0,0,0,0, nullptr,0, nullptr,0);
                k_gemm<64,128,EPI_PLAIN><<<dim3(4,32,2),256,SM_64_128>>>(
                    ROWS,512,768, asp,Wo, 1536,1536, 768,768,MN,
                    t, nullptr,nullptr, 0, 0,0,0,0, nullptr,0, nullptr,0);
                k_lnres<<<ROWS,256>>>(t, t2, res, P[4]+l*DIM, P[5]+l*DIM, res, rsp);
            }
            // FFN
            k_gemm<128,128,EPI_PLAIN><<<dim3(16,16,1),256,SM_128_128>>>(
                ROWS,DFFN,1536, rsp,W1, 1536,1536, 0,0,0,
                nullptr, hsp,nullptr, 0, 0,DFFN,2*DFFN,3*DFFN, P[7]+l*DFFN,1, nullptr,0);
            k_gemm<64,128,EPI_PLAIN><<<dim3(4,32,2),256,SM_64_128>>>(
                ROWS,512,3072, hsp,W2, 6144,6144, 3072,3072,MN,
                t, nullptr,nullptr, 0, 0,0,0,0, P[9]+l*DIM,0, nullptr,0);
            k_lnres<<<ROWS,256>>>(t, t2, res, P[10]+l*DIM, P[11]+l*DIM, res, rsp);
        }
    }

    // ---- final vocab projection ----
    k_gemm<128,128,EPI_PLAIN><<<dim3(250,16,1),256,SM_128_128>>>(
        ROWS,VOCAB,1536, xsp, w+OFF_PJ, 1536,1536, 0,0,0,
        (float*)d_out, nullptr,nullptr, 0, 0,0,0,0, nullptr,0, nullptr,0);
}

// round 9
// speedup vs baseline: 2.7674x; 1.4185x over previous
#include <cuda_runtime.h>
#include <cuda_fp16.h>
#include <math.h>
#include <stdint.h>

typedef __half h16;

#define BATCH 4
#define SEQ   512
#define DIM   512
#define NH    8
#define NL    6
#define DFFN  2048
#define VOCAB 32000
#define ROWS  2048
#define NZ    32

// ---- split-weight stack: weights stored [N][2K] fp16 = [Bh|Bl] -------------
#define QKVL   ((size_t)1536*1024)
#define OFF_QKV 0
#define OFF_WO (NL*QKVL)                            // [512][1024]
#define OFF_W1 (OFF_WO + (size_t)NL*512*1024)       // [2048][1024]
#define OFF_W2 (OFF_W1 + (size_t)NL*2048*1024)      // [512][4096]
#define STACK  (OFF_W2 + (size_t)NL*512*4096)
#define OFF_PJ (2*STACK)
#define WTOT   (OFF_PJ + (size_t)VOCAB*1024)

__device__ __align__(256) h16   g_w  [WTOT];
__device__ __align__(256) float g_x  [ROWS*DIM];
__device__ __align__(256) float g_enc[ROWS*DIM];
__device__ __align__(256) h16   g_xsp[ROWS*2*DIM];        // [Ah|Ah]
__device__ __align__(256) h16   g_esp[ROWS*2*DIM];
__device__ __align__(256) h16   g_qsp[NZ*SEQ*128];        // per-head Q dup
__device__ __align__(256) h16   g_ksp[NZ*SEQ*128];        // per-head K [Kh|Kl]
__device__ __align__(256) float g_v  [ROWS*DIM];
__device__ __align__(256) h16   g_vt [BATCH*DIM*2*SEQ];   // V^T [Vh|Vl]
__device__ __align__(256) float g_sc [NZ*SEQ*SEQ];
__device__ __align__(256) h16   g_psp[NZ*SEQ*2*SEQ];      // probs dup
__device__ __align__(256) h16   g_asp[ROWS*2*DIM];        // attn out dup
__device__ __align__(256) h16   g_hsp[ROWS*2*DFFN];       // FFN hidden dup
__device__ __align__(256) float g_t  [2*ROWS*DIM];        // split-K partials

// ---------------- PTX helpers ------------------------------------------------
__device__ __forceinline__ uint32_t smem_u32(const void* p) {
    uint32_t a;
    asm("{ .reg .u64 t; cvta.to.shared.u64 t, %1; cvt.u32.u64 %0, t; }" : "=r"(a) : "l"(p));
    return a;
}
__device__ __forceinline__ void cpa16(uint32_t dst, const void* src) {
    asm volatile("cp.async.cg.shared.global [%0], [%1], 16;" :: "r"(dst), "l"(src));
}
#define CP_COMMIT() asm volatile("cp.async.commit_group;" ::: "memory")
#define CP_WAIT0()  asm volatile("cp.async.wait_group 0;" ::: "memory")
#define CP_WAIT1()  asm volatile("cp.async.wait_group 1;" ::: "memory")

__device__ __forceinline__ void ldsm4(uint32_t (&r)[4], uint32_t a) {
    asm volatile("ldmatrix.sync.aligned.m8n8.x4.shared.b16 {%0,%1,%2,%3}, [%4];"
        : "=r"(r[0]), "=r"(r[1]), "=r"(r[2]), "=r"(r[3]) : "r"(a));
}
__device__ __forceinline__ void mma16816(float (&d)[4], const uint32_t (&a)[4],
                                         const uint32_t b0, const uint32_t b1) {
    asm volatile("mma.sync.aligned.m16n8k16.row.col.f32.f16.f16.f32 "
        "{%0,%1,%2,%3}, {%4,%5,%6,%7}, {%8,%9}, {%0,%1,%2,%3};"
        : "+f"(d[0]), "+f"(d[1]), "+f"(d[2]), "+f"(d[3])
        : "r"(a[0]), "r"(a[1]), "r"(a[2]), "r"(a[3]), "r"(b0), "r"(b1));
}
__device__ __forceinline__ void split2(float v, h16& h, h16& l) {
    h = __float2half_rn(v);
    l = __float2half_rn(v - __half2float(h));
}

// ---------------- weight transpose + split: src[z,K,N] -> dst[z(dZ),N,2K] ----
__global__ void k_wsplit(const float* __restrict__ s, h16* __restrict__ d,
                         int K, int N, size_t dZ) {
    __shared__ float ts[32][33];
    int n0 = blockIdx.x*32, k0 = blockIdx.y*32;
    s += (size_t)blockIdx.z*K*N;
    d += (size_t)blockIdx.z*dZ;
    int tx = threadIdx.x, ty = threadIdx.y;
#pragma unroll
    for (int i=0;i<4;i++) ts[ty+8*i][tx] = s[(size_t)(k0+ty+8*i)*N + n0+tx];
    __syncthreads();
#pragma unroll
    for (int i=0;i<4;i++) {
        float v = ts[tx][ty+8*i];
        h16 h,l; split2(v,h,l);
        h16* dp = d + (size_t)(n0+ty+8*i)*2*K + k0 + tx;
        dp[0]=h; dp[K]=l;                     // [Bh|Bl]
    }
}

// ---------------- V transpose + split: V[2048][512] -> vt[b][c][2*512] -------
__global__ void k_vt(const float* __restrict__ V, h16* __restrict__ VT) {
    __shared__ float ts[32][33];
    int b = blockIdx.z;
    int s0 = blockIdx.x*32, c0 = blockIdx.y*32;
    int tx = threadIdx.x, ty = threadIdx.y;
#pragma unroll
    for (int i=0;i<4;i++) ts[ty+8*i][tx] = V[((size_t)b*SEQ + s0+ty+8*i)*DIM + c0+tx];
    __syncthreads();
#pragma unroll
    for (int i=0;i<4;i++) {
        float v = ts[tx][ty+8*i];
        h16 h,l; split2(v,h,l);
        h16* dp = VT + ((size_t)b*DIM + c0+ty+8*i)*(2*SEQ) + s0 + tx;
        dp[0]=h; dp[SEQ]=l;                   // [Vh|Vl]
    }
}

// ---------------- unified fp16 mma GEMM --------------------------------------
enum { EPI_PLAIN=0, EPI_QKV=1, EPI_SCORES=2, EPI_AV=3 };

template<int BM, int BN, int MODE>
__global__ void __launch_bounds__(256) k_gemm(
    int M, int N, int KK,
    const h16* __restrict__ A, const h16* __restrict__ B,
    int aRS, int bRS, size_t aZ, size_t bZ, size_t cZ,
    float* __restrict__ C, h16* __restrict__ S, h16* __restrict__ S2,
    int secOff, int sO0, int sO1, int sRS,
    const float* __restrict__ bias, int act,
    const int* __restrict__ tok, int causal)
{
    constexpr int ASZ = BM*128;
    constexpr int BSZ = BN*128;
    constexpr int STG = ASZ+BSZ;
    constexpr int AM  = BM/32;
    constexpr int NT  = BN/32;
    constexpr int WME = BM/2;
    constexpr int WNE = BN/4;
    extern __shared__ char sm[];
    uint32_t smBase = smem_u32(sm);

    int tid=threadIdx.x, lane=tid&31, wid=tid>>5;
    int wm=wid>>2, wn=wid&3;
    int m0=blockIdx.y*BM, n0=blockIdx.x*BN;
    int z=blockIdx.z;
    A += (size_t)z*aZ;
    if (MODE==EPI_AV) B += (((size_t)(z>>3)*DIM) + (size_t)(z&7)*64) * 1024;
    else              B += (size_t)z*bZ;

    float acc[AM][NT][4];
#pragma unroll
    for (int i=0;i<AM;i++)
#pragma unroll
        for (int j=0;j<NT;j++)
#pragma unroll
            for (int r=0;r<4;r++) acc[i][j][r]=0.f;

    auto loadStage = [&](int t, int s) {
        uint32_t st = smBase + s*STG;
        int k0 = t*64;
#pragma unroll
        for (int i=0;i<BM/32;i++) {
            int idx = tid + i*256;
            int r = idx>>3, c = idx&7;
            cpa16(st + r*128 + ((c^(r&7))<<4), A + (size_t)(m0+r)*aRS + k0 + c*8);
        }
#pragma unroll
        for (int i=0;i<BN/32;i++) {
            int idx = tid + i*256;
            int r = idx>>3, c = idx&7;
            cpa16(st + ASZ + r*128 + ((c^(r&7))<<4), B + (size_t)(n0+r)*bRS + k0 + c*8);
        }
    };

    int KT = KK/64;
    loadStage(0,0); CP_COMMIT();
    if (KT>1) { loadStage(1,1); CP_COMMIT(); }

    for (int t=0; t<KT; t++) {
        if (t+2<KT) CP_WAIT1(); else CP_WAIT0();
        __syncthreads();
        if (t+2<KT) { loadStage(t+2, (t+2)%3); CP_COMMIT(); }
        uint32_t aB = smBase + (t%3)*STG;
        uint32_t bB = aB + ASZ;
#pragma unroll
        for (int ks=0; ks<4; ks++) {
            uint32_t af[AM][4];
#pragma unroll
            for (int i=0;i<AM;i++) {
                int r = wm*WME + i*16 + (lane&15);
                int c = ks*2 + (lane>>4);
                ldsm4(af[i], aB + r*128 + ((c^(r&7))<<4));
            }
            uint32_t bfr[NT][2];
#pragma unroll
            for (int j=0;j<NT;j+=2) {
                uint32_t q[4];
                int r = wn*WNE + j*8 + (lane&7) + ((lane>>4)<<3);
                int c = ks*2 + ((lane>>3)&1);
                ldsm4(q, bB + r*128 + ((c^(r&7))<<4));
                bfr[j][0]=q[0]; bfr[j][1]=q[1]; bfr[j+1][0]=q[2]; bfr[j+1][1]=q[3];
            }
#pragma unroll
            for (int i=0;i<AM;i++)
#pragma unroll
                for (int j=0;j<NT;j++)
                    mma16816(acc[i][j], af[i], bfr[j][0], bfr[j][1]);
        }
    }

    // ---- epilogue ----
#pragma unroll
    for (int i=0;i<AM;i++) {
#pragma unroll
        for (int j=0;j<NT;j++) {
#pragma unroll
            for (int r=0;r<4;r++) {
                int row = m0 + wm*WME + i*16 + (lane>>2) + ((r>>1)<<3);
                int col = n0 + wn*WNE + j*8 + ((lane&3)<<1) + (r&1);
                float v = acc[i][j][r];
                if (MODE==EPI_PLAIN) {
                    if (bias && z==0) v += __ldg(&bias[col]);
                    if (act)  v = v>0.f ? v : 0.01f*v;
                    if (C) C[(size_t)z*cZ + (size_t)row*N + col] = v;
                    if (S) {
                        h16 h = __float2half_rn(v);
                        h16* sp = S + (size_t)row*sRS;
                        sp[col+sO0]=h; sp[col+sO1]=h;        // dup hi (A-style)
                    }
                } else if (MODE==EPI_QKV) {
                    int gc = col + secOff;
                    int b = row>>9, s = row&511;
                    if (gc < 512) {            // Q: dup hi per head
                        int h = gc>>6, d = gc&63;
                        h16* sp = S + ((size_t)((b<<3)+h)*512 + s)*128 + d;
                        h16 hh = __float2half_rn(v);
                        sp[0]=hh; sp[64]=hh;
                    } else if (gc < 1024) {    // K: [Kh|Kl] per head
                        int c = gc-512; int h = c>>6, d = c&63;
                        h16* sp = S2 + ((size_t)((b<<3)+h)*512 + s)*128 + d;
                        h16 hh,ll; split2(v,hh,ll);
                        sp[0]=hh; sp[64]=ll;
                    } else {                   // V: fp32 staging
                        C[(size_t)row*512 + gc-1024] = v;
                    }
                } else if (MODE==EPI_SCORES) {
                    bool mk = (tok[(z>>3)*512 + col]==0) || (causal && col>row);
                    C[(size_t)z*cZ + (size_t)row*512 + col] = mk ? 1e-9f : v*0.125f;
                } else {                       // EPI_AV: dup-hi attn out
                    int grow = ((z>>3)<<9) + row;
                    int gcol = ((z&7)<<6) + col;
                    h16 hh = __float2half_rn(v);
                    h16* sp = S + (size_t)grow*1024;
                    sp[gcol]=hh; sp[gcol+512]=hh;
                }
            }
        }
    }
}

// ---------------- embedding + PE ---------------------------------------------
__global__ void k_embed(const int* __restrict__ tok, const float* __restrict__ emb,
                        float* __restrict__ o, h16* __restrict__ os) {
    int idx = blockIdx.x*blockDim.x + threadIdx.x;
    int d = idx&(DIM-1), bs = idx>>9, s = bs&(SEQ-1);
    float pe = 0.f;
    if (s>0 && d>0) {
        double ang = (double)s / pow(10000.0, 2.0*(double)d/(double)DIM);
        pe = (float)((d&1) ? cos(ang) : sin(ang));
    }
    float v = emb[(size_t)tok[bs]*DIM + d] + pe;
    o[idx] = v;
    h16 h = __float2half_rn(v);
    h16* sp = os + (size_t)bs*(2*DIM) + d;
    sp[0]=h; sp[DIM]=h;
}

// ---------------- warp-per-row softmax -> dup-hi probs -----------------------
__global__ void k_softmax(const float* __restrict__ SC, h16* __restrict__ P) {
    int row = blockIdx.x*8 + (threadIdx.x>>5);
    int lane = threadIdx.x&31;
    const float* p = SC + (size_t)row*SEQ;
    float v[16];
#pragma unroll
    for (int i=0;i<4;i++) {
        float4 f = *(const float4*)(p + i*128 + lane*4);
        v[4*i]=f.x; v[4*i+1]=f.y; v[4*i+2]=f.z; v[4*i+3]=f.w;
    }
    float m = v[0];
#pragma unroll
    for (int i=1;i<16;i++) m = fmaxf(m, v[i]);
#pragma unroll
    for (int o=16;o;o>>=1) m = fmaxf(m, __shfl_xor_sync(0xffffffffu, m, o));
    float s = 0.f;
#pragma unroll
    for (int i=0;i<16;i++) { v[i] = expf(v[i]-m); s += v[i]; }
#pragma unroll
    for (int o=16;o;o>>=1) s += __shfl_xor_sync(0xffffffffu, s, o);
    float inv = 1.f/s;
    h16* sp = P + (size_t)row*1024;
#pragma unroll
    for (int i=0;i<4;i++) {
#pragma unroll
        for (int k=0;k<4;k++) {
            int idx = i*128 + lane*4 + k;
            h16 h = __float2half_rn(v[4*i+k]*inv);
            sp[idx]=h; sp[512+idx]=h;
        }
    }
}

// ---------------- residual + LN (sums split-K partials) ----------------------
__global__ void k_lnres(const float* __restrict__ t, const float* __restrict__ t2,
                        const float* __restrict__ r,
                        const float* __restrict__ g, const float* __restrict__ be,
                        float* __restrict__ o, h16* __restrict__ os) {
    int row = blockIdx.x, tid = threadIdx.x;
    __shared__ float red[256];
    size_t o0 = (size_t)row*DIM;
    float a  = t[o0+tid]     + t2[o0+tid]     + r[o0+tid];
    float b2 = t[o0+tid+256] + t2[o0+tid+256] + r[o0+tid+256];
    red[tid] = a+b2;
    __syncthreads();
    for (int s=128;s>0;s>>=1) { if (tid<s) red[tid]+=red[tid+s]; __syncthreads(); }
    float mean = red[0]*(1.f/DIM);
    __syncthreads();
    float da = a-mean, db = b2-mean;
    red[tid] = da*da + db*db;
    __syncthreads();
    for (int s=128;s>0;s>>=1) { if (tid<s) red[tid]+=red[tid+s]; __syncthreads(); }
    float inv = 1.f/sqrtf(red[0]*(1.f/DIM) + 1e-6f);
    float va = da*inv*g[tid] + be[tid];
    float vb = db*inv*g[tid+256] + be[tid+256];
    o[o0+tid] = va; o[o0+tid+256] = vb;
    h16* sp = os + (size_t)row*(2*DIM);
    h16 ha = __float2half_rn(va), hb = __float2half_rn(vb);
    sp[tid]=ha;     sp[DIM+tid]=ha;
    sp[tid+256]=hb; sp[DIM+tid+256]=hb;
}

// ---------------- host --------------------------------------------------------
#define SM_128_128 (3*(128+128)*128)   // 98304
#define SM_64_128  (3*(64+128)*128)    // 73728
#define SM_64_64   (3*(64+64)*128)     // 49152

extern "C" void kernel_launch(void* const* d_in, const int* in_sizes, int n_in,
                              void* d_out, int out_size) {
    const int*   etok = (const int*)d_in[0];
    const int*   dtok = (const int*)d_in[1];
    const float* eemb = (const float*)d_in[2];
    const float* demb = (const float*)d_in[3];
    const float* pw   = (const float*)d_in[4];
    const float* ep[12]; const float* dp[12];
    for (int i=0;i<12;i++) { ep[i]=(const float*)d_in[5+i]; dp[i]=(const float*)d_in[17+i]; }

    cudaFuncSetAttribute(k_gemm<128,128,EPI_PLAIN>,  cudaFuncAttributeMaxDynamicSharedMemorySize, SM_128_128);
    cudaFuncSetAttribute(k_gemm<128,128,EPI_QKV>,    cudaFuncAttributeMaxDynamicSharedMemorySize, SM_128_128);
    cudaFuncSetAttribute(k_gemm<128,128,EPI_SCORES>, cudaFuncAttributeMaxDynamicSharedMemorySize, SM_128_128);
    cudaFuncSetAttribute(k_gemm<64,128,EPI_PLAIN>,   cudaFuncAttributeMaxDynamicSharedMemorySize, SM_64_128);
    cudaFuncSetAttribute(k_gemm<64,128,EPI_QKV>,     cudaFuncAttributeMaxDynamicSharedMemorySize, SM_64_128);
    cudaFuncSetAttribute(k_gemm<64,64,EPI_AV>,       cudaFuncAttributeMaxDynamicSharedMemorySize, SM_64_64);

    h16 *w,*xsp,*esp,*qsp,*ksp,*vt,*psp,*asp,*hsp;
    float *x,*enc,*v,*sc,*t;
    cudaGetSymbolAddress((void**)&w,   g_w);
    cudaGetSymbolAddress((void**)&x,   g_x);   cudaGetSymbolAddress((void**)&enc, g_enc);
    cudaGetSymbolAddress((void**)&xsp, g_xsp); cudaGetSymbolAddress((void**)&esp, g_esp);
    cudaGetSymbolAddress((void**)&qsp, g_qsp); cudaGetSymbolAddress((void**)&ksp, g_ksp);
    cudaGetSymbolAddress((void**)&v,   g_v);   cudaGetSymbolAddress((void**)&vt,  g_vt);
    cudaGetSymbolAddress((void**)&sc,  g_sc);  cudaGetSymbolAddress((void**)&psp, g_psp);
    cudaGetSymbolAddress((void**)&asp, g_asp); cudaGetSymbolAddress((void**)&hsp, g_hsp);
    cudaGetSymbolAddress((void**)&t,   g_t);
    float* t2 = t + (size_t)ROWS*DIM;

    // ---- weight conversion: [K,N] fp32 -> [N,2K] fp16 [Bh|Bl] ----
    dim3 wb(32,8);
    for (int st=0; st<2; st++) {
        const float* const* P = st ? dp : ep;
        h16* wq = w + st*STACK;
        k_wsplit<<<dim3(16,16,NL), wb>>>(P[0], wq+OFF_QKV,            512, 512, QKVL);
        k_wsplit<<<dim3(16,16,NL), wb>>>(P[1], wq+OFF_QKV+ 512*1024,  512, 512, QKVL);
        k_wsplit<<<dim3(16,16,NL), wb>>>(P[2], wq+OFF_QKV+1024*1024,  512, 512, QKVL);
        k_wsplit<<<dim3(16,16,NL), wb>>>(P[3], wq+OFF_WO,             512, 512, (size_t)512*1024);
        k_wsplit<<<dim3(64,16,NL), wb>>>(P[6], wq+OFF_W1,             512, 2048,(size_t)2048*1024);
        k_wsplit<<<dim3(16,64,NL), wb>>>(P[8], wq+OFF_W2,            2048, 512, (size_t)512*4096);
    }
    k_wsplit<<<dim3(1000,16,1), wb>>>(pw, w+OFF_PJ, 512, VOCAB, 0);

    const size_t MN = (size_t)ROWS*DIM;

    for (int st=0; st<2; st++) {
        const int*   tokA = st ? dtok : etok;
        const float* const* P = st ? dp : ep;
        h16*   wq  = w + st*STACK;
        float* res = st ? x : enc;
        h16*   rsp = st ? xsp : esp;

        k_embed<<<(ROWS*DIM)/256,256>>>(tokA, st?demb:eemb, res, rsp);

        for (int l=0; l<NL; l++) {
            const h16* Wqkv = wq + OFF_QKV + l*QKVL;
            const h16* Wo   = wq + OFF_WO + (size_t)l*512*1024;
            const h16* W1   = wq + OFF_W1 + (size_t)l*2048*1024;
            const h16* W2   = wq + OFF_W2 + (size_t)l*512*4096;
            int nAtt = st ? 2 : 1;
            for (int a=0; a<nAtt; a++) {
                const int* tokKV = (st && a==1) ? etok : tokA;
                int causal = (st && a==0) ? 1 : 0;
                if (!st || a==0) {
                    k_gemm<128,128,EPI_QKV><<<dim3(12,16,1),256,SM_128_128>>>(
                        ROWS,1536,1024, rsp,Wqkv, 1024,1024, 0,0,0,
                        v, qsp,ksp, 0, 0,0,0, nullptr,0, nullptr,0);
                } else {
                    k_gemm<64,128,EPI_QKV><<<dim3(4,32,1),256,SM_64_128>>>(
                        ROWS,512,1024, rsp,Wqkv, 1024,1024, 0,0,0,
                        nullptr, qsp,nullptr, 0, 0,0,0, nullptr,0, nullptr,0);
                    k_gemm<128,128,EPI_QKV><<<dim3(8,16,1),256,SM_128_128>>>(
                        ROWS,1024,1024, esp,Wqkv+(size_t)512*1024, 1024,1024, 0,0,0,
                        v, nullptr,ksp, 512, 0,0,0, nullptr,0, nullptr,0);
                }
                k_vt<<<dim3(16,16,BATCH), wb>>>(v, vt);
                k_gemm<128,128,EPI_SCORES><<<dim3(4,4,NZ),256,SM_128_128>>>(
                    SEQ,SEQ,128, qsp,ksp, 128,128, (size_t)SEQ*128,(size_t)SEQ*128,(size_t)SEQ*SEQ,
                    sc, nullptr,nullptr, 0, 0,0,0, nullptr,0, tokKV,causal);
                k_softmax<<<NZ*SEQ/8,256>>>(sc, psp);
                k_gemm<64,64,EPI_AV><<<dim3(1,8,NZ),256,SM_64_64>>>(
                    SEQ,64,1024, psp,vt, 1024,1024, (size_t)SEQ*1024,0,0,
                    nullptr, asp,nullptr, 0, 0,0,0, nullptr,0, nullptr,0);
                k_gemm<64,128,EPI_PLAIN><<<dim3(4,32,2),256,SM_64_128>>>(
                    ROWS,512,512, asp,Wo, 1024,1024, 512,512,MN,
                    t, nullptr,nullptr, 0, 0,0,0, nullptr,0, nullptr,0);
                k_lnres<<<ROWS,256>>>(t, t2, res, P[4]+l*DIM, P[5]+l*DIM, res, rsp);
            }
            // FFN
            k_gemm<128,128,EPI_PLAIN><<<dim3(16,16,1),256,SM_128_128>>>(
                ROWS,DFFN,1024, rsp,W1, 1024,1024, 0,0,0,
                nullptr, hsp,nullptr, 0, 0,DFFN,2*DFFN, P[7]+l*DFFN,1, nullptr,0);
            k_gemm<64,128,EPI_PLAIN><<<dim3(4,32,2),256,SM_64_128>>>(
                ROWS,512,2048, hsp,W2, 4096,4096, 2048,2048,MN,
                t, nullptr,nullptr, 0, 0,0,0, P[9]+l*DIM,0, nullptr,0);
            k_lnres<<<ROWS,256>>>(t, t2, res, P[10]+l*DIM, P[11]+l*DIM, res, rsp);
        }
    }

    // ---- final vocab projection ----
    k_gemm<128,128,EPI_PLAIN><<<dim3(250,16,1),256,SM_128_128>>>(
        ROWS,VOCAB,1024, xsp, w+OFF_PJ, 1024,1024, 0,0,0,
        (float*)d_out, nullptr,nullptr, 0, 0,0,0, nullptr,0, nullptr,0);
}